// round 4
// baseline (speedup 1.0000x reference)
#include <cuda_runtime.h>
#include <cuda_bf16.h>

#define HIDDEN 64
#define N_POS 32
#define K_PATCH 32

// embeddings: rows 0..31 = video positions, rows 32..63 = patches
__device__ float g_emb[64][HIDDEN];

// ---------------------------------------------------------------------------
// Kernel A: conv(4->64, 3x3, SAME) + ReLU + global average pool, one block per
// image. Blocks 0..31 gather the permuted video tile, 32..63 read patches.
// ---------------------------------------------------------------------------
__global__ __launch_bounds__(256)
void conv_emb_kernel(const float* __restrict__ v_latent,
                     const float* __restrict__ p_tensor,
                     const float* __restrict__ v_w,
                     const float* __restrict__ v_b,
                     const float* __restrict__ p_w,
                     const float* __restrict__ p_b)
{
    __shared__ float xs[4][12][10];          // zero-padded input (H=10,W=8 + halo)
    __shared__ float ws[64][4][3][3];        // 2304 floats

    const int img  = blockIdx.x;
    const bool is_v = img < 32;
    const float* __restrict__ w    = is_v ? v_w : p_w;
    const float* __restrict__ bias = is_v ? v_b : p_b;
    const int tid = threadIdx.x;

    // zero padded input + load weights
    for (int i = tid; i < 4 * 12 * 10; i += 256)
        ((float*)xs)[i] = 0.0f;
    for (int i = tid; i < 64 * 4 * 9; i += 256)
        ((float*)ws)[i] = w[i];
    __syncthreads();

    // fill interior: logical x[a][c][e], a=ch(4), c=h(10), e=w(8)
    for (int i = tid; i < 320; i += 256) {
        int e = i & 7;
        int c = (i >> 3) % 10;
        int a = i / 80;
        float val;
        if (is_v) {
            // v_split[pos=b*8+d, a, c, e] = v_latent[a, b, c, d, e]
            int b_ = img >> 3, d = img & 7;
            val = v_latent[(((a * 4 + b_) * 10 + c) * 8 + d) * 8 + e];
        } else {
            val = p_tensor[(img - 32) * 320 + i];
        }
        xs[a][c + 1][e + 1] = val;
    }
    __syncthreads();

    // thread -> (output channel, pixel quarter)
    const int oc  = tid >> 2;       // 0..63
    const int sub = tid & 3;        // 0..3, 20 pixels each

    float wr[4][3][3];
#pragma unroll
    for (int ic = 0; ic < 4; ic++)
#pragma unroll
        for (int kh = 0; kh < 3; kh++)
#pragma unroll
            for (int kw = 0; kw < 3; kw++)
                wr[ic][kh][kw] = ws[oc][ic][kh][kw];
    const float bb = bias[oc];

    float acc = 0.0f;
    const int p0 = sub * 20;
#pragma unroll
    for (int pp = 0; pp < 20; pp++) {
        int p = p0 + pp;
        int h = p >> 3, wc = p & 7;
        float y = bb;
#pragma unroll
        for (int ic = 0; ic < 4; ic++)
#pragma unroll
            for (int kh = 0; kh < 3; kh++)
#pragma unroll
                for (int kw = 0; kw < 3; kw++)
                    y = fmaf(xs[ic][h + kh][wc + kw], wr[ic][kh][kw], y);
        acc += fmaxf(y, 0.0f);
    }
    // reduce the 4 sub-partials (lanes differing only in bits 0..1 share oc)
    acc += __shfl_xor_sync(0xffffffffu, acc, 1);
    acc += __shfl_xor_sync(0xffffffffu, acc, 2);
    if (sub == 0)
        g_emb[img][oc] = acc * (1.0f / 80.0f);
}

// ---------------------------------------------------------------------------
// Kernel B: scores (32x32), stable descending rank, greedy assignment.
// Single block, 1024 threads; greedy is pure warp-register code.
// Output written as FLOAT (harness __output__ dtype is float32).
// ---------------------------------------------------------------------------
__global__ __launch_bounds__(1024)
void match_kernel(float* __restrict__ out)
{
    __shared__ float pe[32][65];   // patch embeddings, padded stride
    __shared__ float ve[32][65];   // video embeddings, padded stride
    __shared__ float sc[32][33];   // scores
    __shared__ int   pref[32][32];

    const int tid = threadIdx.x;

    for (int i = tid; i < 32 * HIDDEN; i += 1024) {
        int r = i >> 6, c = i & 63;
        ve[r][c] = g_emb[r][c];
        pe[r][c] = g_emb[32 + r][c];
    }
    __syncthreads();

    const int p = tid >> 5;   // patch id
    const int v = tid & 31;   // position id

    float s = 0.0f;
#pragma unroll
    for (int i = 0; i < HIDDEN; i++)
        s = fmaf(pe[p][i], ve[v][i], s);
    sc[p][v] = s;
    __syncthreads();

    // stable descending rank: count strictly-greater, plus equal-with-lower-idx
    const float my = sc[p][v];
    int r = 0;
#pragma unroll
    for (int j = 0; j < 32; j++) {
        float o = sc[p][j];
        r += (o > my) || (o == my && j < v);
    }
    pref[p][r] = v;
    __syncthreads();

    // Greedy assignment, warp 0, one lane per pid. Within a sequential round,
    // the lowest unassigned pid wanting an untaken position wins it; positions
    // never become untaken, so per-round min-pid-per-position is exactly the
    // reference's sequential semantics.
    if (tid < 32) {
        const int pid = tid;
        const unsigned full = 0xffffffffu;
        unsigned taken = 0;     // bitmask of taken positions (uniform across lanes)
        int mypos = -1;
#pragma unroll 1
        for (int round = 0; round < 32; round++) {
            int cand = pref[pid][round];
            bool want = (mypos < 0) && !((taken >> cand) & 1u);
            unsigned want_mask = __ballot_sync(full, want);
            unsigned grp = __match_any_sync(full, cand) & want_mask;
            bool won = want && ((grp & ((1u << pid) - 1u)) == 0u);
            if (won) mypos = cand;
            taken |= __reduce_or_sync(full, won ? (1u << cand) : 0u);
            if (__ballot_sync(full, mypos < 0) == 0u) break;
        }
        out[pid] = (float)mypos;   // float32 output dtype
    }
}

extern "C" void kernel_launch(void* const* d_in, const int* in_sizes, int n_in,
                              void* d_out, int out_size)
{
    // Input identification. p_old_idx is the unique 32-element input:
    //   dict/insertion order: [v_latent, p_tensor, p_old_idx, v_w, v_b, p_w, p_b]
    //       sizes:            [10240,    10240,    32,        2304, 64,  2304, 64]
    //   alphabetical order:   [p_b, p_old_idx, p_tensor, p_w, v_b, v_latent, v_w]
    //       sizes:            [64,  32,        10240,    2304, 64, 10240,    2304]
    const float *v_latent, *p_tensor, *v_w, *v_b, *p_w, *p_b;
    if (n_in >= 7 && in_sizes[2] == 32) {
        // dict order
        v_latent = (const float*)d_in[0];
        p_tensor = (const float*)d_in[1];
        v_w      = (const float*)d_in[3];
        v_b      = (const float*)d_in[4];
        p_w      = (const float*)d_in[5];
        p_b      = (const float*)d_in[6];
    } else {
        // alphabetical order
        p_b      = (const float*)d_in[0];
        p_tensor = (const float*)d_in[2];
        p_w      = (const float*)d_in[3];
        v_b      = (const float*)d_in[4];
        v_latent = (const float*)d_in[5];
        v_w      = (const float*)d_in[6];
    }
    float* out = (float*)d_out;

    conv_emb_kernel<<<64, 256>>>(v_latent, p_tensor, v_w, v_b, p_w, p_b);
    match_kernel<<<1, 1024>>>(out);
}

// round 5
// speedup vs baseline: 1.1644x; 1.1644x over previous
#include <cuda_runtime.h>
#include <cuda_bf16.h>

#define HIDDEN 64
#define N_POS 32

// embeddings: rows 0..31 = video positions, rows 32..63 = patches
__device__ float g_emb[64][HIDDEN];
__device__ int   g_count = 0;   // self-resetting cross-block arrival counter

// ---------------------------------------------------------------------------
// Fused kernel: 64 blocks x 256 threads.
//  Phase 1 (all blocks): conv(4->64,3x3,SAME)+ReLU+avgpool for one image.
//  Phase 2 (block 0):    scores -> stable rank -> greedy assign -> d_out.
// ---------------------------------------------------------------------------
__global__ __launch_bounds__(256)
void fused_matcher_kernel(const float* __restrict__ v_latent,
                          const float* __restrict__ p_tensor,
                          const float* __restrict__ v_w,
                          const float* __restrict__ v_b,
                          const float* __restrict__ p_w,
                          const float* __restrict__ p_b,
                          float* __restrict__ out)
{
    __shared__ float xs[4][12][10];     // zero-padded input (H=10,W=8 + halo)
    __shared__ float ws[64][4][3][3];   // conv weights
    // match-phase smem (block 0 only)
    __shared__ float4 pe4[32 * 17];     // patch emb, 68-float row stride
    __shared__ float4 ve4[32 * 17];     // video emb, 68-float row stride
    __shared__ float  sc[32][33];
    __shared__ int    pref[32][32];

    const int img  = blockIdx.x;
    const bool is_v = img < 32;
    const float* __restrict__ w    = is_v ? v_w : p_w;
    const float* __restrict__ bias = is_v ? v_b : p_b;
    const int tid = threadIdx.x;

    // ---------------- Phase 1: conv + relu + avgpool ----------------
    for (int i = tid; i < 4 * 12 * 10; i += 256)
        ((float*)xs)[i] = 0.0f;
    for (int i = tid; i < 64 * 4 * 9; i += 256)
        ((float*)ws)[i] = w[i];
    __syncthreads();

    // interior: logical x[a][c][e], a=ch(4), c=h(10), e=w(8)
    for (int i = tid; i < 320; i += 256) {
        int e = i & 7;
        int c = (i >> 3) % 10;
        int a = i / 80;
        float val;
        if (is_v) {
            // v_split[pos=b*8+d, a, c, e] = v_latent[a, b, c, d, e]
            int b_ = img >> 3, d = img & 7;
            val = v_latent[(((a * 4 + b_) * 10 + c) * 8 + d) * 8 + e];
        } else {
            val = p_tensor[(img - 32) * 320 + i];
        }
        xs[a][c + 1][e + 1] = val;
    }
    __syncthreads();

    const int oc  = tid >> 2;   // 0..63
    const int sub = tid & 3;    // 0..3, 20 pixels each

    float wr[4][3][3];
#pragma unroll
    for (int ic = 0; ic < 4; ic++)
#pragma unroll
        for (int kh = 0; kh < 3; kh++)
#pragma unroll
            for (int kw = 0; kw < 3; kw++)
                wr[ic][kh][kw] = ws[oc][ic][kh][kw];
    const float bb = bias[oc];

    float acc = 0.0f;
    const int p0 = sub * 20;
#pragma unroll
    for (int pp = 0; pp < 20; pp++) {
        int p = p0 + pp;
        int h = p >> 3, wc = p & 7;
        float y = bb;
#pragma unroll
        for (int ic = 0; ic < 4; ic++)
#pragma unroll
            for (int kh = 0; kh < 3; kh++)
#pragma unroll
                for (int kw = 0; kw < 3; kw++)
                    y = fmaf(xs[ic][h + kh][wc + kw], wr[ic][kh][kw], y);
        acc += fmaxf(y, 0.0f);
    }
    acc += __shfl_xor_sync(0xffffffffu, acc, 1);
    acc += __shfl_xor_sync(0xffffffffu, acc, 2);
    if (sub == 0)
        g_emb[img][oc] = acc * (1.0f / 80.0f);

    __syncthreads();   // all of this block's g_emb stores issued

    if (img != 0) {
        if (tid == 0) {
            __threadfence();              // release our g_emb row
            atomicAdd(&g_count, 1);
        }
        return;
    }

    // ---------------- Phase 2 (block 0 only): match ----------------
    if (tid == 0) {
        while (atomicAdd(&g_count, 0) != 63) { }   // acquire-spin
    }
    __syncthreads();
    __threadfence();   // all threads: acquire before reading g_emb

    // load embeddings into padded smem (L2 reads; bypass L1)
    for (int i = tid; i < 32 * HIDDEN; i += 256) {
        int r = i >> 6, c = i & 63;
        ((float*)ve4)[r * 68 + c] = __ldcg(&g_emb[r][c]);
        ((float*)pe4)[r * 68 + c] = __ldcg(&g_emb[32 + r][c]);
    }
    __syncthreads();

    // scores: 1024 dot products, 4 per thread; warp = patch, lane = position
#pragma unroll
    for (int rep = 0; rep < 4; rep++) {
        int idx = tid + rep * 256;
        int p = idx >> 5, v = idx & 31;
        float s = 0.0f;
#pragma unroll
        for (int i = 0; i < 16; i++) {
            float4 a = pe4[p * 17 + i];   // broadcast within warp
            float4 b = ve4[v * 17 + i];   // conflict-free (stride 17 f4)
            s = fmaf(a.x, b.x, s);
            s = fmaf(a.y, b.y, s);
            s = fmaf(a.z, b.z, s);
            s = fmaf(a.w, b.w, s);
        }
        sc[p][v] = s;
    }
    __syncthreads();

    // stable descending rank: strictly-greater, plus equal-with-lower-idx
#pragma unroll
    for (int rep = 0; rep < 4; rep++) {
        int idx = tid + rep * 256;
        int p = idx >> 5, v = idx & 31;
        const float my = sc[p][v];
        int r = 0;
#pragma unroll
        for (int j = 0; j < 32; j++) {
            float o = sc[p][j];
            r += (o > my) || (o == my && j < v);
        }
        pref[p][r] = v;
    }
    __syncthreads();

    // greedy assignment, warp 0, one lane per pid. Round-sequential semantics
    // == per-round min-pid-per-untaken-position (positions never free up).
    if (tid < 32) {
        const int pid = tid;
        const unsigned full = 0xffffffffu;
        unsigned taken = 0;
        int mypos = -1;
#pragma unroll 1
        for (int round = 0; round < 32; round++) {
            int cand = pref[pid][round];
            bool want = (mypos < 0) && !((taken >> cand) & 1u);
            unsigned want_mask = __ballot_sync(full, want);
            unsigned grp = __match_any_sync(full, cand) & want_mask;
            bool won = want && ((grp & ((1u << pid) - 1u)) == 0u);
            if (won) mypos = cand;
            taken |= __reduce_or_sync(full, won ? (1u << cand) : 0u);
            if (__ballot_sync(full, mypos < 0) == 0u) break;
        }
        out[pid] = (float)mypos;   // float32 output dtype
    }

    // reset counter for next replay (all 63 adds already observed)
    if (tid == 0) atomicExch(&g_count, 0);
}

extern "C" void kernel_launch(void* const* d_in, const int* in_sizes, int n_in,
                              void* d_out, int out_size)
{
    // Input identification. p_old_idx is the unique 32-element input:
    //   dict/insertion order: [v_latent, p_tensor, p_old_idx, v_w, v_b, p_w, p_b]
    //   alphabetical order:   [p_b, p_old_idx, p_tensor, p_w, v_b, v_latent, v_w]
    const float *v_latent, *p_tensor, *v_w, *v_b, *p_w, *p_b;
    if (n_in >= 7 && in_sizes[2] == 32) {
        v_latent = (const float*)d_in[0];
        p_tensor = (const float*)d_in[1];
        v_w      = (const float*)d_in[3];
        v_b      = (const float*)d_in[4];
        p_w      = (const float*)d_in[5];
        p_b      = (const float*)d_in[6];
    } else {
        p_b      = (const float*)d_in[0];
        p_tensor = (const float*)d_in[2];
        p_w      = (const float*)d_in[3];
        v_b      = (const float*)d_in[4];
        v_latent = (const float*)d_in[5];
        v_w      = (const float*)d_in[6];
    }
    float* out = (float*)d_out;

    fused_matcher_kernel<<<64, 256>>>(v_latent, p_tensor, v_w, v_b, p_w, p_b, out);
}

// round 6
// speedup vs baseline: 1.4411x; 1.2376x over previous
#include <cuda_runtime.h>
#include <cuda_bf16.h>

#define HIDDEN 64
#define N_POS 32

// embeddings: rows 0..31 = video positions, rows 32..63 = patches
__device__ float g_emb[64][HIDDEN];
__device__ int   g_count = 0;   // self-resetting cross-block arrival counter

// ---------------------------------------------------------------------------
// Fused kernel: 128 blocks x 320 threads.
//  Phase 1 (all blocks): half the output channels of conv(4->64,3x3,SAME)
//                        +ReLU+avgpool for one image. blockIdx: img*2+half.
//  Phase 2 (block 0):    scores -> stable rank -> greedy assign -> d_out.
// ---------------------------------------------------------------------------
__global__ __launch_bounds__(320)
void fused_matcher_kernel(const float* __restrict__ v_latent,
                          const float* __restrict__ p_tensor,
                          const float* __restrict__ v_w,
                          const float* __restrict__ v_b,
                          const float* __restrict__ p_w,
                          const float* __restrict__ p_b,
                          float* __restrict__ out)
{
    __shared__ float xs[4][12][10];     // zero-padded input (H=10,W=8 + halo)
    __shared__ float ws[32 * 37];       // 32 oc x 36 weights, stride 37 (bank-free)
    __shared__ float psum[10][32];      // per-row partial sums
    // match-phase smem (block 0 only)
    __shared__ float4 pe4[32 * 17];     // patch emb, 68-float row stride
    __shared__ float4 ve4[32 * 17];     // video emb, 68-float row stride
    __shared__ float  sc[32][33];
    __shared__ int    pref[32][32];

    const int img  = blockIdx.x >> 1;
    const int half = blockIdx.x & 1;    // which 32 output channels
    const bool is_v = img < 32;
    const float* __restrict__ w    = (is_v ? v_w : p_w) + half * 32 * 36;
    const float* __restrict__ bias = (is_v ? v_b : p_b) + half * 32;
    const int tid = threadIdx.x;

    // ---------------- Phase 1: conv + relu + avgpool ----------------
    for (int i = tid; i < 4 * 12 * 10; i += 320)
        ((float*)xs)[i] = 0.0f;
    for (int i = tid; i < 32 * 36; i += 320)
        ws[(i / 36) * 37 + (i % 36)] = w[i];
    __syncthreads();

    // interior: logical x[a][c][e], a=ch(4), c=h(10), e=w(8)
    if (tid < 320) {
        int i = tid;
        int e = i & 7;
        int c = (i >> 3) % 10;
        int a = i / 80;
        float val;
        if (is_v) {
            // v_split[pos=b*8+d, a, c, e] = v_latent[a, b, c, d, e]
            int b_ = img >> 3, d = img & 7;
            val = v_latent[(((a * 4 + b_) * 10 + c) * 8 + d) * 8 + e];
        } else {
            val = p_tensor[(img - 32) * 320 + i];
        }
        xs[a][c + 1][e + 1] = val;
    }
    __syncthreads();

    // lane = oc (broadcast xs loads), warp-group = row
    const int row = tid >> 5;   // 0..9
    const int oc  = tid & 31;   // 0..31 (local)

    float wr[4][3][3];
#pragma unroll
    for (int ic = 0; ic < 4; ic++)
#pragma unroll
        for (int kh = 0; kh < 3; kh++)
#pragma unroll
            for (int kw = 0; kw < 3; kw++)
                wr[ic][kh][kw] = ws[oc * 37 + (ic * 3 + kh) * 3 + kw];
    const float bb = bias[oc];

    float acc = 0.0f;
#pragma unroll
    for (int wc = 0; wc < 8; wc++) {
        float y = bb;
#pragma unroll
        for (int ic = 0; ic < 4; ic++)
#pragma unroll
            for (int kh = 0; kh < 3; kh++)
#pragma unroll
                for (int kw = 0; kw < 3; kw++)
                    y = fmaf(xs[ic][row + kh][wc + kw], wr[ic][kh][kw], y);
        acc += fmaxf(y, 0.0f);
    }
    psum[row][oc] = acc;
    __syncthreads();

    if (tid < 32) {
        float s = 0.0f;
#pragma unroll
        for (int r = 0; r < 10; r++)
            s += psum[r][tid];
        g_emb[img][half * 32 + tid] = s * (1.0f / 80.0f);
    }
    __syncthreads();   // stores issued

    if (blockIdx.x != 0) {
        if (tid == 0) {
            __threadfence();              // release our g_emb stores
            atomicAdd(&g_count, 1);
        }
        return;
    }

    // ---------------- Phase 2 (block 0 only): match ----------------
    if (tid == 0) {
        while (atomicAdd(&g_count, 0) != 127) { }   // acquire-spin
    }
    __syncthreads();
    __threadfence();   // acquire before reading g_emb

    // load embeddings into padded smem (bypass L1)
    for (int i = tid; i < 32 * HIDDEN; i += 320) {
        int r = i >> 6, c = i & 63;
        ((float*)ve4)[r * 68 + c] = __ldcg(&g_emb[r][c]);
        ((float*)pe4)[r * 68 + c] = __ldcg(&g_emb[32 + r][c]);
    }
    __syncthreads();

    // scores: 1024 dot products; warp = patch, lane = position
    if (tid < 256) {
#pragma unroll
        for (int rep = 0; rep < 4; rep++) {
            int idx = tid + rep * 256;
            int p = idx >> 5, v = idx & 31;
            float s = 0.0f;
#pragma unroll
            for (int i = 0; i < 16; i++) {
                float4 a = pe4[p * 17 + i];   // broadcast within warp
                float4 b = ve4[v * 17 + i];   // conflict-free (stride 17 f4)
                s = fmaf(a.x, b.x, s);
                s = fmaf(a.y, b.y, s);
                s = fmaf(a.z, b.z, s);
                s = fmaf(a.w, b.w, s);
            }
            sc[p][v] = s;
        }
    }
    __syncthreads();

    // stable descending rank: strictly-greater, plus equal-with-lower-idx
    if (tid < 256) {
#pragma unroll
        for (int rep = 0; rep < 4; rep++) {
            int idx = tid + rep * 256;
            int p = idx >> 5, v = idx & 31;
            const float my = sc[p][v];
            int r = 0;
#pragma unroll
            for (int j = 0; j < 32; j++) {
                float o = sc[p][j];
                r += (o > my) || (o == my && j < v);
            }
            pref[p][r] = v;
        }
    }
    __syncthreads();

    // greedy assignment, warp 0, one lane per pid. Round-sequential semantics
    // == per-round min-pid-per-untaken-position (positions never free up).
    if (tid < 32) {
        const int pid = tid;
        const unsigned full = 0xffffffffu;
        unsigned taken = 0;
        int mypos = -1;
#pragma unroll 1
        for (int round = 0; round < 32; round++) {
            int cand = pref[pid][round];
            bool want = (mypos < 0) && !((taken >> cand) & 1u);
            unsigned want_mask = __ballot_sync(full, want);
            unsigned grp = __match_any_sync(full, cand) & want_mask;
            bool won = want && ((grp & ((1u << pid) - 1u)) == 0u);
            if (won) mypos = cand;
            taken |= __reduce_or_sync(full, won ? (1u << cand) : 0u);
            if (__ballot_sync(full, mypos < 0) == 0u) break;
        }
        out[pid] = (float)mypos;   // float32 output dtype
    }

    // reset counter for next replay (all 127 adds already observed)
    if (tid == 0) atomicExch(&g_count, 0);
}

extern "C" void kernel_launch(void* const* d_in, const int* in_sizes, int n_in,
                              void* d_out, int out_size)
{
    // Input identification. p_old_idx is the unique 32-element input:
    //   dict/insertion order: [v_latent, p_tensor, p_old_idx, v_w, v_b, p_w, p_b]
    //   alphabetical order:   [p_b, p_old_idx, p_tensor, p_w, v_b, v_latent, v_w]
    const float *v_latent, *p_tensor, *v_w, *v_b, *p_w, *p_b;
    if (n_in >= 7 && in_sizes[2] == 32) {
        v_latent = (const float*)d_in[0];
        p_tensor = (const float*)d_in[1];
        v_w      = (const float*)d_in[3];
        v_b      = (const float*)d_in[4];
        p_w      = (const float*)d_in[5];
        p_b      = (const float*)d_in[6];
    } else {
        p_b      = (const float*)d_in[0];
        p_tensor = (const float*)d_in[2];
        p_w      = (const float*)d_in[3];
        v_b      = (const float*)d_in[4];
        v_latent = (const float*)d_in[5];
        v_w      = (const float*)d_in[6];
    }
    float* out = (float*)d_out;

    fused_matcher_kernel<<<128, 320>>>(v_latent, p_tensor, v_w, v_b, p_w, p_b, out);
}

// round 8
// speedup vs baseline: 1.4747x; 1.0233x over previous
#include <cuda_runtime.h>
#include <cuda_bf16.h>

#define HIDDEN 64
#define N_POS 32

// embeddings: rows 0..31 = video positions, rows 32..63 = patches
__device__ float g_emb[64][HIDDEN];
__device__ int   g_count = 0;   // self-resetting cross-block arrival counter

// ---------------------------------------------------------------------------
// Fused kernel: 128 blocks x 320 threads.
//  Phase 1 (all blocks): half the output channels of conv(4->64,3x3,SAME)
//                        +ReLU+avgpool for one image. blockIdx: img*2+half.
//  Phase 2 (block 0):    scores+rank (register/shfl) -> greedy -> d_out.
// ---------------------------------------------------------------------------
__global__ __launch_bounds__(320)
void fused_matcher_kernel(const float* __restrict__ v_latent,
                          const float* __restrict__ p_tensor,
                          const float* __restrict__ v_w,
                          const float* __restrict__ v_b,
                          const float* __restrict__ p_w,
                          const float* __restrict__ p_b,
                          float* __restrict__ out)
{
    // 16B alignment is REQUIRED: rows are read below as float2 (LDS.64).
    __shared__ __align__(16) float xs[4][12][10];  // zero-padded input
    __shared__ float ws[32 * 37];       // 32 oc x 36 weights, stride 37 (bank-free)
    __shared__ float psum[10][32];      // per-row partial sums
    // match-phase smem (block 0 only)
    __shared__ float4 pe4[32 * 17];     // patch emb, 68-float row stride
    __shared__ float4 ve4[32 * 17];     // video emb, 68-float row stride
    __shared__ int    pref[32][32];

    const int img  = blockIdx.x >> 1;
    const int half = blockIdx.x & 1;    // which 32 output channels
    const bool is_v = img < 32;
    const float* __restrict__ w    = (is_v ? v_w : p_w) + half * 32 * 36;
    const float* __restrict__ bias = (is_v ? v_b : p_b) + half * 32;
    const int tid  = threadIdx.x;
    const int lane = tid & 31;

    // ---------------- Phase 1: conv + relu + avgpool ----------------
    for (int i = tid; i < 4 * 12 * 10; i += 320)
        ((float*)xs)[i] = 0.0f;
    for (int i = tid; i < 32 * 36; i += 320)
        ws[(i / 36) * 37 + (i % 36)] = w[i];
    __syncthreads();

    // interior: logical x[a][c][e], a=ch(4), c=h(10), e=w(8)
    {
        int i = tid;   // 320 threads == 320 elements
        int e = i & 7;
        int c = (i >> 3) % 10;
        int a = i / 80;
        float val;
        if (is_v) {
            // v_split[pos=b*8+d, a, c, e] = v_latent[a, b, c, d, e]
            int b_ = img >> 3, d = img & 7;
            val = v_latent[(((a * 4 + b_) * 10 + c) * 8 + d) * 8 + e];
        } else {
            val = p_tensor[(img - 32) * 320 + i];
        }
        xs[a][c + 1][e + 1] = val;
    }
    __syncthreads();

    // lane = oc (broadcast xs loads), warp = output row
    const int row = tid >> 5;   // 0..9
    const int oc  = lane;       // 0..31 (local)

    float wr[4][3][3];
#pragma unroll
    for (int ic = 0; ic < 4; ic++)
#pragma unroll
        for (int kh = 0; kh < 3; kh++)
#pragma unroll
            for (int kw = 0; kw < 3; kw++)
                wr[ic][kh][kw] = ws[oc * 37 + (ic * 3 + kh) * 3 + kw];
    const float bb = bias[oc];

    float y[8];
#pragma unroll
    for (int wc = 0; wc < 8; wc++) y[wc] = bb;

    // sliding-window: per (ic,kh) load the 10-float row once (5 x LDS.64).
    // Row byte offset = (ic*12 + row + kh) * 40, 8B-aligned given 16B base.
#pragma unroll
    for (int ic = 0; ic < 4; ic++) {
#pragma unroll
        for (int kh = 0; kh < 3; kh++) {
            const float2* xrow = (const float2*)&xs[ic][row + kh][0];
            float x[10];
#pragma unroll
            for (int t = 0; t < 5; t++) {
                float2 v2 = xrow[t];
                x[2 * t]     = v2.x;
                x[2 * t + 1] = v2.y;
            }
#pragma unroll
            for (int wc = 0; wc < 8; wc++)
#pragma unroll
                for (int kw = 0; kw < 3; kw++)
                    y[wc] = fmaf(x[wc + kw], wr[ic][kh][kw], y[wc]);
        }
    }
    float acc = 0.0f;
#pragma unroll
    for (int wc = 0; wc < 8; wc++)
        acc += fmaxf(y[wc], 0.0f);
    psum[row][oc] = acc;
    __syncthreads();

    if (tid < 32) {
        float s = 0.0f;
#pragma unroll
        for (int r = 0; r < 10; r++)
            s += psum[r][tid];
        g_emb[img][half * 32 + tid] = s * (1.0f / 80.0f);
    }
    __syncthreads();   // stores issued

    if (blockIdx.x != 0) {
        if (tid == 0) {
            __threadfence();              // release our g_emb stores
            atomicAdd(&g_count, 1);
        }
        return;
    }

    // ---------------- Phase 2 (block 0 only): match ----------------
    if (tid == 0) {
        while (atomicAdd(&g_count, 0) != 127) { }   // proven L2-atomic poll
    }
    __syncthreads();
    __threadfence();   // acquire before reading g_emb

    // load embeddings into padded smem via float4 (bypass L1)
    for (int i = tid; i < 32 * 16; i += 320) {
        int r = i >> 4, c = i & 15;
        ve4[r * 17 + c] = __ldcg((const float4*)&g_emb[r][c * 4]);
        pe4[r * 17 + c] = __ldcg((const float4*)&g_emb[32 + r][c * 4]);
    }
    __syncthreads();

    // scores + stable descending rank, fully in registers.
    // warp w (0..7) handles patches 4w..4w+3; lane = position v.
    const int wid = tid >> 5;
    const unsigned full = 0xffffffffu;
    if (wid < 8) {
        const int v = lane;
#pragma unroll
        for (int pp = 0; pp < 4; pp++) {
            const int p = wid * 4 + pp;
            float s = 0.0f;
#pragma unroll
            for (int i = 0; i < 16; i++) {
                float4 a = pe4[p * 17 + i];   // broadcast within warp
                float4 b = ve4[v * 17 + i];   // conflict-free (stride 17 f4)
                s = fmaf(a.x, b.x, s);
                s = fmaf(a.y, b.y, s);
                s = fmaf(a.z, b.z, s);
                s = fmaf(a.w, b.w, s);
            }
            // rank among the 32 scores of patch p (stable, descending)
            const float my = s;
            int r = 0;
#pragma unroll
            for (int j = 0; j < 32; j++) {
                float o = __shfl_sync(full, s, j);
                r += (o > my) || (o == my && j < v);
            }
            pref[p][r] = v;
        }
    }
    __syncthreads();

    // greedy assignment, warp 0, one lane per pid. Round-sequential semantics
    // == per-round min-pid-per-untaken-position (positions never free up).
    if (tid < 32) {
        const int pid = tid;
        unsigned taken = 0;
        int mypos = -1;
#pragma unroll 1
        for (int round = 0; round < 32; round++) {
            int cand = pref[pid][round];
            bool want = (mypos < 0) && !((taken >> cand) & 1u);
            unsigned want_mask = __ballot_sync(full, want);
            unsigned grp = __match_any_sync(full, cand) & want_mask;
            bool won = want && ((grp & ((1u << pid) - 1u)) == 0u);
            if (won) mypos = cand;
            taken |= __reduce_or_sync(full, won ? (1u << cand) : 0u);
            if (__ballot_sync(full, mypos < 0) == 0u) break;
        }
        out[pid] = (float)mypos;   // float32 output dtype
    }

    // reset counter for next replay (all 127 adds already observed)
    if (tid == 0) atomicExch(&g_count, 0);
}

extern "C" void kernel_launch(void* const* d_in, const int* in_sizes, int n_in,
                              void* d_out, int out_size)
{
    // Input identification. p_old_idx is the unique 32-element input:
    //   dict/insertion order: [v_latent, p_tensor, p_old_idx, v_w, v_b, p_w, p_b]
    //   alphabetical order:   [p_b, p_old_idx, p_tensor, p_w, v_b, v_latent, v_w]
    const float *v_latent, *p_tensor, *v_w, *v_b, *p_w, *p_b;
    if (n_in >= 7 && in_sizes[2] == 32) {
        v_latent = (const float*)d_in[0];
        p_tensor = (const float*)d_in[1];
        v_w      = (const float*)d_in[3];
        v_b      = (const float*)d_in[4];
        p_w      = (const float*)d_in[5];
        p_b      = (const float*)d_in[6];
    } else {
        p_b      = (const float*)d_in[0];
        p_tensor = (const float*)d_in[2];
        p_w      = (const float*)d_in[3];
        v_b      = (const float*)d_in[4];
        v_latent = (const float*)d_in[5];
        v_w      = (const float*)d_in[6];
    }
    float* out = (float*)d_out;

    fused_matcher_kernel<<<128, 320>>>(v_latent, p_tensor, v_w, v_b, p_w, p_b, out);
}